// round 14
// baseline (speedup 1.0000x reference)
#include <cuda_runtime.h>
#include <cuda_fp16.h>
#include <math.h>
#include <stdint.h>

#define BT   4096
#define KK   64
#define DD   256
#define PP   4
#define KPP  16

// A-side packed hi|lo per 16-k chunk: [row][chunk][16 hi | 16 lo] halves (row stride 2048)
__device__ __align__(16) __half u_pk[(size_t)BT * 2048];
__device__ __align__(16) __half z_pk[(size_t)BT * 2048];
// B-side plain fp16 row-major
__device__ __align__(16) __half pw_h[4 * 256 * 256];
__device__ __align__(16) __half qw_h[256 * 1024];
__device__ __align__(16) float s4_g[(size_t)4 * BT * 256];
__device__ __align__(16) float gv_g[1024];
__device__ float cst_g[8];

__device__ __forceinline__ uint32_t smem_u32(const void* p) {
    uint32_t a;
    asm("{ .reg .u64 t; cvta.to.shared.u64 t, %1; cvt.u32.u64 %0, t; }" : "=r"(a) : "l"(p));
    return a;
}
__device__ __forceinline__ void cp16(uint32_t dst, const void* src) {
    size_t g;
    asm("cvta.to.global.u64 %0, %1;" : "=l"(g) : "l"(src));
    asm volatile("cp.async.cg.shared.global [%0], [%1], 16;" :: "r"(dst), "l"(g) : "memory");
}
#define CP_COMMIT() asm volatile("cp.async.commit_group;" ::: "memory")
#define CP_WAIT2()  asm volatile("cp.async.wait_group 2;" ::: "memory")

#define MMA_F16(d, a, b0, b1) \
    asm volatile("mma.sync.aligned.m16n8k16.row.col.f32.f16.f16.f32 " \
        "{%0,%1,%2,%3}, {%4,%5,%6,%7}, {%8,%9}, {%0,%1,%2,%3};" \
        : "+f"((d)[0]), "+f"((d)[1]), "+f"((d)[2]), "+f"((d)[3]) \
        : "r"((a)[0]), "r"((a)[1]), "r"((a)[2]), "r"((a)[3]), "r"(b0), "r"(b1))

__device__ __forceinline__ void ldm_x4(uint32_t* r, uint32_t a) {
    asm volatile("ldmatrix.sync.aligned.m8n8.x4.shared.b16 {%0,%1,%2,%3}, [%4];"
                 : "=r"(r[0]), "=r"(r[1]), "=r"(r[2]), "=r"(r[3]) : "r"(a));
}
__device__ __forceinline__ void hsplit(float x, __half& h, __half& l) {
    h = __float2half_rn(x);
    l = __float2half_rn(x - __half2float(h));
}
__device__ __forceinline__ void store_pk(__half* base, size_t row, int k,
                                         float v0, float v1) {
    const size_t dst = row * 2048 + (size_t)((k >> 4) * 32 + (k & 15));
    __half h0, l0, h1, l1;
    hsplit(v0, h0, l0); hsplit(v1, h1, l1);
    __half2 hp; hp.x = h0; hp.y = h1;
    __half2 lp; lp.x = l0; lp.y = l1;
    *(__half2*)(base + dst)      = hp;
    *(__half2*)(base + dst + 16) = lp;
}

// ===================== K1: weighted segment-sum -> u_pk =====================
__global__ __launch_bounds__(256)
void k_seg(const float* __restrict__ E_S, const float* __restrict__ W,
           const int* __restrict__ part_idx)
{
    __shared__ float w_s[2 * KK];
    __shared__ float winv_s[2 * PP];
    __shared__ int   pidx_s[KK];

    const int tid = threadIdx.x;
    const int bx  = blockIdx.x;
    const int row0 = bx * 2;

    if (tid < KK)  pidx_s[tid] = part_idx[tid];
    if (tid < 2 * KK) w_s[tid] = W[(size_t)row0 * KK + tid];
    __syncthreads();
    if (tid < 2 * PP) {
        int r = tid >> 2, p = tid & 3;
        float s = 0.f;
#pragma unroll
        for (int kp = 0; kp < KPP; kp++) s += w_s[r * KK + pidx_s[p * KPP + kp]];
        winv_s[tid] = 1.0f / (s + 1e-6f);
    }
    __syncthreads();

    const int p0 = tid >> 6;
    const int d4 = tid & 63;
    const float4* Ea = (const float4*)(E_S + (size_t)row0 * KK * DD);
    const float4* Eb = Ea + (KK * DD / 4);

    float4 aa = make_float4(0.f,0.f,0.f,0.f);
    float4 ab = make_float4(0.f,0.f,0.f,0.f);
#pragma unroll
    for (int kp = 0; kp < KPP; kp++) {
        const int k  = pidx_s[p0 * KPP + kp];
        const float wa = w_s[k];
        const float wb = w_s[KK + k];
        const float4 ea = Ea[k * 64 + d4];
        const float4 eb = Eb[k * 64 + d4];
        aa.x = fmaf(wa, ea.x, aa.x); aa.y = fmaf(wa, ea.y, aa.y);
        aa.z = fmaf(wa, ea.z, aa.z); aa.w = fmaf(wa, ea.w, aa.w);
        ab.x = fmaf(wb, eb.x, ab.x); ab.y = fmaf(wb, eb.y, ab.y);
        ab.z = fmaf(wb, eb.z, ab.z); ab.w = fmaf(wb, eb.w, ab.w);
    }
    const float iva = winv_s[p0];
    const float ivb = winv_s[PP + p0];
    aa.x *= iva; aa.y *= iva; aa.z *= iva; aa.w *= iva;
    ab.x *= ivb; ab.y *= ivb; ab.z *= ivb; ab.w *= ivb;

    const int kk = p0 * 256 + d4 * 4;
    store_pk(u_pk, row0,     kk,     aa.x, aa.y);
    store_pk(u_pk, row0,     kk + 2, aa.z, aa.w);
    store_pk(u_pk, row0 + 1, kk,     ab.x, ab.y);
    store_pk(u_pk, row0 + 1, kk + 2, ab.z, ab.w);
}

// ===================== prep: gv/cst + weight fp16 convert ===================
__global__ void k_prep(const float* __restrict__ v, const float* __restrict__ c,
                       const float* __restrict__ ln_g, const float* __restrict__ ln_b)
{
    const int tid = threadIdx.x;             // 128
    const int p = tid >> 5, lane = tid & 31;
    float s4 = 0.f, s5 = 0.f;
#pragma unroll
    for (int i = 0; i < 8; i++) {
        const int col = p * 256 + lane + i * 32;
        const float vv = v[col];
        const float g  = ln_g[col] * vv;
        const float b  = ln_b[col] * vv;
        gv_g[col] = g;
        s4 += g; s5 += b;
    }
#pragma unroll
    for (int off = 16; off; off >>= 1) {
        s4 += __shfl_xor_sync(0xffffffffu, s4, off);
        s5 += __shfl_xor_sync(0xffffffffu, s5, off);
    }
    if (lane == 0) { cst_g[p] = s4; cst_g[4 + p] = s5 + c[p]; }
}

__global__ __launch_bounds__(256)
void k_wconv(const float* __restrict__ part_W, const float* __restrict__ proj_W)
{
    const int i0 = blockIdx.x * 256 + threadIdx.x;
#pragma unroll
    for (int j = 0; j < 2; j++) {
        const int i = i0 + j * 262144;
        if (i < 262144) pw_h[i] = __float2half_rn(part_W[i]);
        else            qw_h[i - 262144] = __float2half_rn(proj_W[i - 262144]);
    }
}

// ===================== 64x256-tile fp16 HMMA GEMM, 4-deep ring ==============
// A smem row pitch 80B: [hi q0 | hi q1 | lo q0 | lo q1 | pad16]; 64 rows = 5120
// B smem row pitch 48B: [q0 | q1 | pad16]; 256 rows = 12288
#define APITCH 80
#define BPITCH 48
#define ASTG   5120
#define STG    17408
#define SM_TBL  (4 * STG)           // 69632
#define SM_BIAS (SM_TBL)
#define SM_GVS  (SM_TBL + 1024)
#define SM_STATS (SM_TBL + 2048)
#define SM_ALPH (SM_TBL + 2048 + 3072)
#define GEMM_SMEM (SM_ALPH + 256)

__global__ __launch_bounds__(256, 3)
void k_gemm(const float* __restrict__ part_b_, int mode)
{
    extern __shared__ char sm[];
    float* bias_s  = (float*)(sm + SM_BIAS);
    float* gvs_s   = (float*)(sm + SM_GVS);
    float* stats_s = (float*)(sm + SM_STATS);   // [64][12]
    float* alpha_s = (float*)(sm + SM_ALPH);    // [64]

    const int tid = threadIdx.x;
    const int w = tid >> 5, lane = tid & 31;
    const int gid = lane >> 2, tig = lane & 3;
    const int m0 = blockIdx.x * 64;
    const int by = blockIdx.y;     // mode0: part; mode1: K-split

    const __half *Asrc, *Bsrc;
    int aCh0, bCh0, bRowStride;
    if (mode == 0) {
        Asrc = u_pk; aCh0 = by * 16;
        Bsrc = pw_h + by * 65536; bRowStride = 256; bCh0 = 0;
        bias_s[tid] = part_b_[by * 256 + tid];
        gvs_s[tid]  = gv_g[by * 256 + tid];
    } else {
        Asrc = z_pk; aCh0 = by * 16;
        Bsrc = qw_h; bRowStride = 1024; bCh0 = by * 16;
    }

    float acc[2][8][4];
#pragma unroll
    for (int mt = 0; mt < 2; mt++)
#pragma unroll
        for (int nt = 0; nt < 8; nt++)
#pragma unroll
            for (int q = 0; q < 4; q++) acc[mt][nt][q] = 0.f;

    auto issue = [&](int c) {
        if (c < 16) {
            char* base = sm + (c & 3) * STG;
#pragma unroll
            for (int j = 0; j < 3; j++) {
                const int s = tid + j * 256;
                if (s < 256) {          // A: 64 rows x 4 (hi q0,q1 / lo q0,q1)
                    const int row = s >> 2, q = s & 3;
                    cp16(smem_u32(base + row * APITCH + q * 16),
                         Asrc + (size_t)(m0 + row) * 2048 + (aCh0 + c) * 32 + q * 8);
                } else {                // B: 256 rows x 2 quadrants
                    const int t = s - 256;
                    const int row = t >> 1, q = t & 1;
                    cp16(smem_u32(base + ASTG + row * BPITCH + q * 16),
                         Bsrc + (size_t)row * bRowStride + (bCh0 + c) * 16 + q * 8);
                }
            }
        }
        CP_COMMIT();
    };

    issue(0); issue(1); issue(2);

    const int mrow = (w & 1) * 32;
    const int ncol = (w >> 1) * 64;
    const int lr = lane & 7, lq = lane >> 3;

#pragma unroll 1
    for (int c = 0; c < 16; c++) {
        CP_WAIT2();
        __syncthreads();
        issue(c + 3);

        char* base = sm + (c & 3) * STG;
        uint32_t ah[2][4], al[2][4];
#pragma unroll
        for (int mt = 0; mt < 2; mt++) {
            const uint32_t a = smem_u32(base + (mrow + mt * 16 + (lq & 1) * 8 + lr) * APITCH
                                        + (lq >> 1) * 16);
            ldm_x4(ah[mt], a);
            ldm_x4(al[mt], a + 32);
        }
#pragma unroll
        for (int np = 0; np < 2; np++) {       // pairs of n-tile-pairs
            uint32_t bh[2][4];
#pragma unroll
            for (int e = 0; e < 2; e++) {
                const int nt2 = np * 2 + e;
                const uint32_t b = smem_u32(base + ASTG
                                   + (ncol + nt2 * 16 + (lq >> 1) * 8 + lr) * BPITCH
                                   + (lq & 1) * 16);
                ldm_x4(bh[e], b);
            }
#pragma unroll
            for (int e = 0; e < 2; e++) {      // combo hh
                const int nt2 = np * 2 + e;
                MMA_F16(acc[0][2*nt2],   ah[0], bh[e][0], bh[e][1]);
                MMA_F16(acc[0][2*nt2+1], ah[0], bh[e][2], bh[e][3]);
                MMA_F16(acc[1][2*nt2],   ah[1], bh[e][0], bh[e][1]);
                MMA_F16(acc[1][2*nt2+1], ah[1], bh[e][2], bh[e][3]);
            }
#pragma unroll
            for (int e = 0; e < 2; e++) {      // combo lh (A residual)
                const int nt2 = np * 2 + e;
                MMA_F16(acc[0][2*nt2],   al[0], bh[e][0], bh[e][1]);
                MMA_F16(acc[0][2*nt2+1], al[0], bh[e][2], bh[e][3]);
                MMA_F16(acc[1][2*nt2],   al[1], bh[e][0], bh[e][1]);
                MMA_F16(acc[1][2*nt2+1], al[1], bh[e][2], bh[e][3]);
            }
        }
    }

    if (mode == 0) {
        // ---- fused gate epilogue ----
        float s1[4], s2[4], s3[4];
#pragma unroll
        for (int i = 0; i < 4; i++) { s1[i] = 0.f; s2[i] = 0.f; s3[i] = 0.f; }
#pragma unroll
        for (int mt = 0; mt < 2; mt++)
#pragma unroll
            for (int nt = 0; nt < 8; nt++) {
                const int c0 = ncol + nt * 8 + tig * 2;
                const float b0 = bias_s[c0], b1 = bias_s[c0 + 1];
                const float g0 = gvs_s[c0],  g1 = gvs_s[c0 + 1];
                const float x0 = acc[mt][nt][0] + b0, x1 = acc[mt][nt][1] + b1;
                const float x2 = acc[mt][nt][2] + b0, x3 = acc[mt][nt][3] + b1;
                acc[mt][nt][0] = x0; acc[mt][nt][1] = x1;
                acc[mt][nt][2] = x2; acc[mt][nt][3] = x3;
                const int i0 = mt * 2, i1 = mt * 2 + 1;
                s1[i0] += x0 + x1; s2[i0] += x0*x0 + x1*x1; s3[i0] += x0*g0 + x1*g1;
                s1[i1] += x2 + x3; s2[i1] += x2*x2 + x3*x3; s3[i1] += x2*g0 + x3*g1;
            }
#pragma unroll
        for (int i = 0; i < 4; i++) {
#pragma unroll
            for (int off = 1; off < 4; off <<= 1) {
                s1[i] += __shfl_xor_sync(0xffffffffu, s1[i], off);
                s2[i] += __shfl_xor_sync(0xffffffffu, s2[i], off);
                s3[i] += __shfl_xor_sync(0xffffffffu, s3[i], off);
            }
        }
        const int cg = w >> 1;
        if (tig == 0) {
#pragma unroll
            for (int i = 0; i < 4; i++) {
                const int row = mrow + (i >> 1) * 16 + (i & 1) * 8 + gid;
                stats_s[row * 12 + cg * 3 + 0] = s1[i];
                stats_s[row * 12 + cg * 3 + 1] = s2[i];
                stats_s[row * 12 + cg * 3 + 2] = s3[i];
            }
        }
        __syncthreads();
        if (tid < 64) {
            float S1 = 0.f, S2 = 0.f, S3 = 0.f;
#pragma unroll
            for (int g = 0; g < 4; g++) {
                S1 += stats_s[tid * 12 + g * 3 + 0];
                S2 += stats_s[tid * 12 + g * 3 + 1];
                S3 += stats_s[tid * 12 + g * 3 + 2];
            }
            const float m   = S1 * (1.0f / DD);
            const float var = S2 * (1.0f / DD) - m * m;
            const float rs  = rsqrtf(var + 1e-5f);
            const float dot = rs * (S3 - m * cst_g[by]) + cst_g[4 + by];
            alpha_s[tid] = 1.0f / (1.0f + __expf(-dot));
        }
        __syncthreads();
#pragma unroll
        for (int mt = 0; mt < 2; mt++) {
            const int rA = mrow + mt * 16 + gid;
            const float alA = alpha_s[rA], alB = alpha_s[rA + 8];
#pragma unroll
            for (int nt = 0; nt < 8; nt++) {
                const int c0 = ncol + nt * 8 + tig * 2;
                const int k  = by * 256 + c0;
                store_pk(z_pk, (size_t)(m0 + rA),     k, acc[mt][nt][0] * alA, acc[mt][nt][1] * alA);
                store_pk(z_pk, (size_t)(m0 + rA + 8), k, acc[mt][nt][2] * alB, acc[mt][nt][3] * alB);
            }
        }
    } else {
        float* outp = s4_g + (size_t)by * BT * 256;
#pragma unroll
        for (int mt = 0; mt < 2; mt++) {
            const int r0 = m0 + mrow + mt * 16 + gid;
#pragma unroll
            for (int nt = 0; nt < 8; nt++) {
                const int c0 = ncol + nt * 8 + tig * 2;
                *(float2*)(outp + (size_t)r0 * 256 + c0) =
                    make_float2(acc[mt][nt][0], acc[mt][nt][1]);
                *(float2*)(outp + (size_t)(r0 + 8) * 256 + c0) =
                    make_float2(acc[mt][nt][2], acc[mt][nt][3]);
            }
        }
    }
}

// ===================== combine K-split partials + final LN ==================
__global__ __launch_bounds__(256)
void k_comb(const float* __restrict__ pjb, const float* __restrict__ og_,
            const float* __restrict__ ob_, float* __restrict__ out)
{
    __shared__ float redf[16 * 8 * 2];
    const int tid = threadIdx.x;
    const int w = tid >> 5, lane = tid & 31;
    const int bt0 = blockIdx.x * 16;

    const float b = pjb[tid];
    float x[16];
#pragma unroll
    for (int r = 0; r < 16; r++) {
        const size_t off = (size_t)(bt0 + r) * 256 + tid;
        x[r] = s4_g[off] + s4_g[off + (size_t)BT * 256]
             + s4_g[off + (size_t)2 * BT * 256] + s4_g[off + (size_t)3 * BT * 256] + b;
    }
#pragma unroll
    for (int r = 0; r < 16; r++) {
        float s1 = x[r], s2 = x[r] * x[r];
#pragma unroll
        for (int off = 16; off; off >>= 1) {
            s1 += __shfl_xor_sync(0xffffffffu, s1, off);
            s2 += __shfl_xor_sync(0xffffffffu, s2, off);
        }
        if (lane == 0) {
            redf[(r * 8 + w) * 2 + 0] = s1;
            redf[(r * 8 + w) * 2 + 1] = s2;
        }
    }
    __syncthreads();
    const float og = og_[tid], ob = ob_[tid];
#pragma unroll
    for (int r = 0; r < 16; r++) {
        float s1 = 0.f, s2 = 0.f;
#pragma unroll
        for (int ww = 0; ww < 8; ww++) {
            s1 += redf[(r * 8 + ww) * 2 + 0];
            s2 += redf[(r * 8 + ww) * 2 + 1];
        }
        const float m   = s1 * (1.0f / DD);
        const float var = s2 * (1.0f / DD) - m * m;
        const float rs  = rsqrtf(var + 1e-5f);
        out[(size_t)(bt0 + r) * 256 + tid] = (x[r] - m) * rs * og + ob;
    }
}

extern "C" void kernel_launch(void* const* d_in, const int* in_sizes, int n_in,
                              void* d_out, int out_size)
{
    (void)in_sizes; (void)n_in; (void)out_size;
    const float* E_S    = (const float*)d_in[0];
    const float* W      = (const float*)d_in[1];
    const int*   pidx   = (const int*)  d_in[2];
    const float* part_W = (const float*)d_in[3];
    const float* part_b = (const float*)d_in[4];
    const float* v      = (const float*)d_in[5];
    const float* c      = (const float*)d_in[6];
    const float* ln_g   = (const float*)d_in[7];
    const float* ln_b   = (const float*)d_in[8];
    const float* proj_W = (const float*)d_in[9];
    const float* proj_b = (const float*)d_in[10];
    const float* out_g  = (const float*)d_in[11];
    const float* out_b  = (const float*)d_in[12];
    float* out = (float*)d_out;

    cudaFuncSetAttribute(k_gemm, cudaFuncAttributeMaxDynamicSharedMemorySize, GEMM_SMEM);

    k_prep<<<1, 128>>>(v, c, ln_g, ln_b);
    k_wconv<<<1024, 256>>>(part_W, proj_W);
    k_seg<<<BT / 2, 256>>>(E_S, W, pidx);
    k_gemm<<<dim3(64, 4), 256, GEMM_SMEM>>>(part_b, 0);
    k_gemm<<<dim3(64, 4), 256, GEMM_SMEM>>>(part_b, 1);
    k_comb<<<BT / 16, 256>>>(proj_b, out_g, out_b, out);
}

// round 15
// speedup vs baseline: 1.0929x; 1.0929x over previous
#include <cuda_runtime.h>
#include <cuda_bf16.h>
#include <math.h>
#include <stdint.h>

#define BT   4096
#define KK   64
#define DD   256
#define PP   4
#define KPP  16

// packed hi|lo per 16-k chunk: [row][chunk][16 hi | 16 lo] bf16 (row stride 2048)
__device__ __align__(16) __nv_bfloat16 u_pk[(size_t)BT * 2048];
__device__ __align__(16) __nv_bfloat16 z_pk[(size_t)BT * 2048];
__device__ __align__(16) __nv_bfloat16 pw_pk[1024 * 512];
__device__ __align__(16) __nv_bfloat16 qw_pk[256 * 2048];
__device__ __align__(16) float s4_g[(size_t)4 * BT * 256];
__device__ __align__(16) float gv_g[1024];
__device__ float cst_g[8];

__device__ __forceinline__ uint32_t smem_u32(const void* p) {
    uint32_t a;
    asm("{ .reg .u64 t; cvta.to.shared.u64 t, %1; cvt.u32.u64 %0, t; }" : "=r"(a) : "l"(p));
    return a;
}
__device__ __forceinline__ void cp16(uint32_t dst, const void* src) {
    size_t g;
    asm("cvta.to.global.u64 %0, %1;" : "=l"(g) : "l"(src));
    asm volatile("cp.async.cg.shared.global [%0], [%1], 16;" :: "r"(dst), "l"(g) : "memory");
}
#define CP_COMMIT() asm volatile("cp.async.commit_group;" ::: "memory")
#define CP_WAIT2()  asm volatile("cp.async.wait_group 2;" ::: "memory")

#define MMA_BF16(d, a, b0, b1) \
    asm volatile("mma.sync.aligned.m16n8k16.row.col.f32.bf16.bf16.f32 " \
        "{%0,%1,%2,%3}, {%4,%5,%6,%7}, {%8,%9}, {%0,%1,%2,%3};" \
        : "+f"((d)[0]), "+f"((d)[1]), "+f"((d)[2]), "+f"((d)[3]) \
        : "r"((a)[0]), "r"((a)[1]), "r"((a)[2]), "r"((a)[3]), "r"(b0), "r"(b1))

__device__ __forceinline__ void ldm_x4(uint32_t* r, uint32_t a) {
    asm volatile("ldmatrix.sync.aligned.m8n8.x4.shared.b16 {%0,%1,%2,%3}, [%4];"
                 : "=r"(r[0]), "=r"(r[1]), "=r"(r[2]), "=r"(r[3]) : "r"(a));
}
__device__ __forceinline__ void bsplit(float x, __nv_bfloat16& h, __nv_bfloat16& l) {
    h = __float2bfloat16(x);
    l = __float2bfloat16(x - __bfloat162float(h));
}
__device__ __forceinline__ void store_pk(__nv_bfloat16* base, size_t row, int k,
                                         float v0, float v1) {
    const size_t dst = row * 2048 + (size_t)((k >> 4) * 32 + (k & 15));
    __nv_bfloat16 h0, l0, h1, l1;
    bsplit(v0, h0, l0); bsplit(v1, h1, l1);
    __nv_bfloat162 hp; hp.x = h0; hp.y = h1;
    __nv_bfloat162 lp; lp.x = l0; lp.y = l1;
    *(__nv_bfloat162*)(base + dst)      = hp;
    *(__nv_bfloat162*)(base + dst + 16) = lp;
}

// ===================== K1: weighted segment-sum -> u_pk =====================
__global__ __launch_bounds__(256)
void k_seg(const float* __restrict__ E_S, const float* __restrict__ W,
           const int* __restrict__ part_idx)
{
    __shared__ float w_s[2 * KK];
    __shared__ float winv_s[2 * PP];
    __shared__ int   pidx_s[KK];

    const int tid = threadIdx.x;
    const int bx  = blockIdx.x;
    const int row0 = bx * 2;

    if (tid < KK)  pidx_s[tid] = part_idx[tid];
    if (tid < 2 * KK) w_s[tid] = W[(size_t)row0 * KK + tid];
    __syncthreads();
    if (tid < 2 * PP) {
        int r = tid >> 2, p = tid & 3;
        float s = 0.f;
#pragma unroll
        for (int kp = 0; kp < KPP; kp++) s += w_s[r * KK + pidx_s[p * KPP + kp]];
        winv_s[tid] = 1.0f / (s + 1e-6f);
    }
    __syncthreads();

    const int p0 = tid >> 6;
    const int d4 = tid & 63;
    const float4* Ea = (const float4*)(E_S + (size_t)row0 * KK * DD);
    const float4* Eb = Ea + (KK * DD / 4);

    float4 aa = make_float4(0.f,0.f,0.f,0.f);
    float4 ab = make_float4(0.f,0.f,0.f,0.f);
#pragma unroll
    for (int kp = 0; kp < KPP; kp++) {
        const int k  = pidx_s[p0 * KPP + kp];
        const float wa = w_s[k];
        const float wb = w_s[KK + k];
        const float4 ea = Ea[k * 64 + d4];
        const float4 eb = Eb[k * 64 + d4];
        aa.x = fmaf(wa, ea.x, aa.x); aa.y = fmaf(wa, ea.y, aa.y);
        aa.z = fmaf(wa, ea.z, aa.z); aa.w = fmaf(wa, ea.w, aa.w);
        ab.x = fmaf(wb, eb.x, ab.x); ab.y = fmaf(wb, eb.y, ab.y);
        ab.z = fmaf(wb, eb.z, ab.z); ab.w = fmaf(wb, eb.w, ab.w);
    }
    const float iva = winv_s[p0];
    const float ivb = winv_s[PP + p0];
    aa.x *= iva; aa.y *= iva; aa.z *= iva; aa.w *= iva;
    ab.x *= ivb; ab.y *= ivb; ab.z *= ivb; ab.w *= ivb;

    const int kk = p0 * 256 + d4 * 4;
    store_pk(u_pk, row0,     kk,     aa.x, aa.y);
    store_pk(u_pk, row0,     kk + 2, aa.z, aa.w);
    store_pk(u_pk, row0 + 1, kk,     ab.x, ab.y);
    store_pk(u_pk, row0 + 1, kk + 2, ab.z, ab.w);
}

// ===================== prep: gv/cst + weight split+pack =====================
__global__ void k_prep(const float* __restrict__ v, const float* __restrict__ c,
                       const float* __restrict__ ln_g, const float* __restrict__ ln_b)
{
    const int tid = threadIdx.x;             // 128
    const int p = tid >> 5, lane = tid & 31;
    float s4 = 0.f, s5 = 0.f;
#pragma unroll
    for (int i = 0; i < 8; i++) {
        const int col = p * 256 + lane + i * 32;
        const float vv = v[col];
        const float g  = ln_g[col] * vv;
        const float b  = ln_b[col] * vv;
        gv_g[col] = g;
        s4 += g; s5 += b;
    }
#pragma unroll
    for (int off = 16; off; off >>= 1) {
        s4 += __shfl_xor_sync(0xffffffffu, s4, off);
        s5 += __shfl_xor_sync(0xffffffffu, s5, off);
    }
    if (lane == 0) { cst_g[p] = s4; cst_g[4 + p] = s5 + c[p]; }
}

__global__ __launch_bounds__(256)
void k_wconv(const float* __restrict__ part_W, const float* __restrict__ proj_W)
{
    const int i0 = blockIdx.x * 256 + threadIdx.x;
#pragma unroll
    for (int j = 0; j < 4; j++) {
        const int i = i0 + j * 131072;
        if (i < 262144) {
            const int row = i >> 8, k = i & 255;
            __nv_bfloat16 h, l; bsplit(part_W[i], h, l);
            const int dst = row * 512 + (k >> 4) * 32 + (k & 15);
            pw_pk[dst] = h; pw_pk[dst + 16] = l;
        } else {
            const int q = i - 262144;
            const int row = q >> 10, k = q & 1023;
            __nv_bfloat16 h, l; bsplit(proj_W[q], h, l);
            const int dst = row * 2048 + (k >> 4) * 32 + (k & 15);
            qw_pk[dst] = h; qw_pk[dst + 16] = l;
        }
    }
}

// ===================== 64x256-tile bf16 GEMM, 512 thr, 4-deep ring ==========
// smem row pitch 80B: [hi q0 | hi q1 | lo q0 | lo q1 | pad16]
// stage: A 64*80=5120 | B 256*80=20480 -> 25600; 4 stages = 102400
#define PITCH 80
#define ASTG  5120
#define STG   25600
#define SM_TBL   102400
#define SM_BIAS  (SM_TBL)
#define SM_GVS   (SM_TBL + 1024)
#define SM_STATS (SM_TBL + 2048)
#define SM_ALPH  (SM_TBL + 2048 + 3072)
#define GEMM_SMEM (SM_ALPH + 256)

__global__ __launch_bounds__(512, 2)
void k_gemm(const float* __restrict__ part_b_, int mode)
{
    extern __shared__ char sm[];
    float* bias_s  = (float*)(sm + SM_BIAS);
    float* gvs_s   = (float*)(sm + SM_GVS);
    float* stats_s = (float*)(sm + SM_STATS);   // [64][12]
    float* alpha_s = (float*)(sm + SM_ALPH);    // [64]

    const int tid = threadIdx.x;
    const int w = tid >> 5, lane = tid & 31;
    const int gid = lane >> 2, tig = lane & 3;
    const int m0 = blockIdx.x * 64;
    const int by = blockIdx.y;     // mode0: part; mode1: K-split

    const __nv_bfloat16 *Asrc, *Bsrc;
    int aCh0, bCh0, bRowStride;
    if (mode == 0) {
        Asrc = u_pk; aCh0 = by * 16;
        Bsrc = pw_pk + by * 256 * 512; bRowStride = 512; bCh0 = 0;
        if (tid < 256) {
            bias_s[tid] = part_b_[by * 256 + tid];
            gvs_s[tid]  = gv_g[by * 256 + tid];
        }
    } else {
        Asrc = z_pk; aCh0 = by * 16;
        Bsrc = qw_pk; bRowStride = 2048; bCh0 = by * 16;
    }

    // warp tile: 16 rows x 64 cols. w&3 = m-group, w>>2 = n-group.
    const int mrow = (w & 3) * 16;
    const int ncol = (w >> 2) * 64;
    const int lr = lane & 7, lq = lane >> 3;

    float acc[8][4];
#pragma unroll
    for (int nt = 0; nt < 8; nt++)
#pragma unroll
        for (int q = 0; q < 4; q++) acc[nt][q] = 0.f;

    auto issue = [&](int c) {
        if (c < 16) {
            char* base = sm + (c & 3) * STG;
#pragma unroll
            for (int j = 0; j < 3; j++) {
                const int s = tid + j * 512;
                if (s < 256) {               // A: 64 rows x 4 slots
                    const int row = s >> 2, q = s & 3;
                    cp16(smem_u32(base + row * PITCH + q * 16),
                         Asrc + (size_t)(m0 + row) * 2048 + (aCh0 + c) * 32 + q * 8);
                } else if (s < 1280) {       // B: 256 rows x 4 slots
                    const int t = s - 256;
                    const int row = t >> 2, q = t & 3;
                    cp16(smem_u32(base + ASTG + row * PITCH + q * 16),
                         Bsrc + (size_t)row * bRowStride + (bCh0 + c) * 32 + q * 8);
                }
            }
        }
        CP_COMMIT();
    };

    issue(0); issue(1); issue(2);

#pragma unroll 1
    for (int c = 0; c < 16; c++) {
        CP_WAIT2();
        __syncthreads();
        issue(c + 3);

        char* base = sm + (c & 3) * STG;
        uint32_t ah[4], al[4];
        {
            const uint32_t a = smem_u32(base + (mrow + (lq & 1) * 8 + lr) * PITCH
                                        + (lq >> 1) * 16);
            ldm_x4(ah, a);
            ldm_x4(al, a + 32);
        }
#pragma unroll
        for (int np = 0; np < 2; np++) {
            uint32_t bh[2][4], bl[2][4];
#pragma unroll
            for (int e = 0; e < 2; e++) {
                const int nt2 = np * 2 + e;
                const uint32_t b = smem_u32(base + ASTG
                                   + (ncol + nt2 * 16 + (lq >> 1) * 8 + lr) * PITCH
                                   + (lq & 1) * 16);
                ldm_x4(bh[e], b);
                ldm_x4(bl[e], b + 32);
            }
#pragma unroll
            for (int e = 0; e < 2; e++) {
                const int nt2 = np * 2 + e;
                MMA_BF16(acc[2*nt2],   ah, bh[e][0], bh[e][1]);
                MMA_BF16(acc[2*nt2+1], ah, bh[e][2], bh[e][3]);
            }
#pragma unroll
            for (int e = 0; e < 2; e++) {
                const int nt2 = np * 2 + e;
                MMA_BF16(acc[2*nt2],   ah, bl[e][0], bl[e][1]);
                MMA_BF16(acc[2*nt2+1], ah, bl[e][2], bl[e][3]);
            }
#pragma unroll
            for (int e = 0; e < 2; e++) {
                const int nt2 = np * 2 + e;
                MMA_BF16(acc[2*nt2],   al, bh[e][0], bh[e][1]);
                MMA_BF16(acc[2*nt2+1], al, bh[e][2], bh[e][3]);
            }
        }
    }

    if (mode == 0) {
        // ---- fused gate epilogue (2 rows/thread: mrow+gid, mrow+gid+8) ----
        float s1[2], s2[2], s3[2];
        s1[0]=s1[1]=s2[0]=s2[1]=s3[0]=s3[1]=0.f;
#pragma unroll
        for (int nt = 0; nt < 8; nt++) {
            const int c0 = ncol + nt * 8 + tig * 2;
            const float b0 = bias_s[c0], b1 = bias_s[c0 + 1];
            const float g0 = gvs_s[c0],  g1 = gvs_s[c0 + 1];
            const float x0 = acc[nt][0] + b0, x1 = acc[nt][1] + b1;
            const float x2 = acc[nt][2] + b0, x3 = acc[nt][3] + b1;
            acc[nt][0] = x0; acc[nt][1] = x1; acc[nt][2] = x2; acc[nt][3] = x3;
            s1[0] += x0 + x1; s2[0] += x0*x0 + x1*x1; s3[0] += x0*g0 + x1*g1;
            s1[1] += x2 + x3; s2[1] += x2*x2 + x3*x3; s3[1] += x2*g0 + x3*g1;
        }
#pragma unroll
        for (int i = 0; i < 2; i++) {
#pragma unroll
            for (int off = 1; off < 4; off <<= 1) {
                s1[i] += __shfl_xor_sync(0xffffffffu, s1[i], off);
                s2[i] += __shfl_xor_sync(0xffffffffu, s2[i], off);
                s3[i] += __shfl_xor_sync(0xffffffffu, s3[i], off);
            }
        }
        const int cg = w >> 2;
        if (tig == 0) {
#pragma unroll
            for (int i = 0; i < 2; i++) {
                const int row = mrow + i * 8 + gid;
                stats_s[row * 12 + cg * 3 + 0] = s1[i];
                stats_s[row * 12 + cg * 3 + 1] = s2[i];
                stats_s[row * 12 + cg * 3 + 2] = s3[i];
            }
        }
        __syncthreads();
        if (tid < 64) {
            float S1 = 0.f, S2 = 0.f, S3 = 0.f;
#pragma unroll
            for (int g = 0; g < 4; g++) {
                S1 += stats_s[tid * 12 + g * 3 + 0];
                S2 += stats_s[tid * 12 + g * 3 + 1];
                S3 += stats_s[tid * 12 + g * 3 + 2];
            }
            const float m   = S1 * (1.0f / DD);
            const float var = S2 * (1.0f / DD) - m * m;
            const float rs  = rsqrtf(var + 1e-5f);
            const float dot = rs * (S3 - m * cst_g[by]) + cst_g[4 + by];
            alpha_s[tid] = 1.0f / (1.0f + __expf(-dot));
        }
        __syncthreads();
        const int rA = mrow + gid;
        const float alA = alpha_s[rA], alB = alpha_s[rA + 8];
#pragma unroll
        for (int nt = 0; nt < 8; nt++) {
            const int c0 = ncol + nt * 8 + tig * 2;
            const int k  = by * 256 + c0;
            store_pk(z_pk, (size_t)(m0 + rA),     k, acc[nt][0] * alA, acc[nt][1] * alA);
            store_pk(z_pk, (size_t)(m0 + rA + 8), k, acc[nt][2] * alB, acc[nt][3] * alB);
        }
    } else {
        float* outp = s4_g + (size_t)by * BT * 256;
        const int r0 = m0 + mrow + gid;
#pragma unroll
        for (int nt = 0; nt < 8; nt++) {
            const int c0 = ncol + nt * 8 + tig * 2;
            *(float2*)(outp + (size_t)r0 * 256 + c0) =
                make_float2(acc[nt][0], acc[nt][1]);
            *(float2*)(outp + (size_t)(r0 + 8) * 256 + c0) =
                make_float2(acc[nt][2], acc[nt][3]);
        }
    }
}

// ===================== combine K-split partials + final LN ==================
__global__ __launch_bounds__(256)
void k_comb(const float* __restrict__ pjb, const float* __restrict__ og_,
            const float* __restrict__ ob_, float* __restrict__ out)
{
    __shared__ float redf[16 * 8 * 2];
    const int tid = threadIdx.x;
    const int w = tid >> 5, lane = tid & 31;
    const int bt0 = blockIdx.x * 16;

    const float b = pjb[tid];
    float x[16];
#pragma unroll
    for (int r = 0; r < 16; r++) {
        const size_t off = (size_t)(bt0 + r) * 256 + tid;
        x[r] = s4_g[off] + s4_g[off + (size_t)BT * 256]
             + s4_g[off + (size_t)2 * BT * 256] + s4_g[off + (size_t)3 * BT * 256] + b;
    }
#pragma unroll
    for (int r = 0; r < 16; r++) {
        float s1 = x[r], s2 = x[r] * x[r];
#pragma unroll
        for (int off = 16; off; off >>= 1) {
            s1 += __shfl_xor_sync(0xffffffffu, s1, off);
            s2 += __shfl_xor_sync(0xffffffffu, s2, off);
        }
        if (lane == 0) {
            redf[(r * 8 + w) * 2 + 0] = s1;
            redf[(r * 8 + w) * 2 + 1] = s2;
        }
    }
    __syncthreads();
    const float og = og_[tid], ob = ob_[tid];
#pragma unroll
    for (int r = 0; r < 16; r++) {
        float s1 = 0.f, s2 = 0.f;
#pragma unroll
        for (int ww = 0; ww < 8; ww++) {
            s1 += redf[(r * 8 + ww) * 2 + 0];
            s2 += redf[(r * 8 + ww) * 2 + 1];
        }
        const float m   = s1 * (1.0f / DD);
        const float var = s2 * (1.0f / DD) - m * m;
        const float rs  = rsqrtf(var + 1e-5f);
        out[(size_t)(bt0 + r) * 256 + tid] = (x[r] - m) * rs * og + ob;
    }
}

extern "C" void kernel_launch(void* const* d_in, const int* in_sizes, int n_in,
                              void* d_out, int out_size)
{
    (void)in_sizes; (void)n_in; (void)out_size;
    const float* E_S    = (const float*)d_in[0];
    const float* W      = (const float*)d_in[1];
    const int*   pidx   = (const int*)  d_in[2];
    const float* part_W = (const float*)d_in[3];
    const float* part_b = (const float*)d_in[4];
    const float* v      = (const float*)d_in[5];
    const float* c      = (const float*)d_in[6];
    const float* ln_g   = (const float*)d_in[7];
    const float* ln_b   = (const float*)d_in[8];
    const float* proj_W = (const float*)d_in[9];
    const float* proj_b = (const float*)d_in[10];
    const float* out_g  = (const float*)d_in[11];
    const float* out_b  = (const float*)d_in[12];
    float* out = (float*)d_out;

    cudaFuncSetAttribute(k_gemm, cudaFuncAttributeMaxDynamicSharedMemorySize, GEMM_SMEM);

    k_prep<<<1, 128>>>(v, c, ln_g, ln_b);
    k_wconv<<<512, 256>>>(part_W, proj_W);
    k_seg<<<BT / 2, 256>>>(E_S, W, pidx);
    k_gemm<<<dim3(64, 4), 512, GEMM_SMEM>>>(part_b, 0);
    k_gemm<<<dim3(64, 4), 512, GEMM_SMEM>>>(part_b, 1);
    k_comb<<<BT / 16, 256>>>(proj_b, out_g, out_b, out);
}

// round 16
// speedup vs baseline: 1.3396x; 1.2257x over previous
#include <cuda_runtime.h>
#include <cuda_fp16.h>
#include <math.h>
#include <stdint.h>

#define BT   4096
#define KK   64
#define DD   256
#define PP   4
#define KPP  16

// A-side packed hi|lo per 16-k chunk: [row][chunk][16 hi | 16 lo] fp16 (row stride 2048)
__device__ __align__(16) __half u_pk[(size_t)BT * 2048];
__device__ __align__(16) __half z_pk[(size_t)BT * 2048];
// B-side: same chunked layout, hi slots only (lo slots unused)
__device__ __align__(16) __half pw_pk[1024 * 512];
__device__ __align__(16) __half qw_pk[256 * 2048];
__device__ __align__(16) float s4_g[(size_t)4 * BT * 256];
__device__ __align__(16) float gv_g[1024];
__device__ float cst_g[8];

__device__ __forceinline__ uint32_t smem_u32(const void* p) {
    uint32_t a;
    asm("{ .reg .u64 t; cvta.to.shared.u64 t, %1; cvt.u32.u64 %0, t; }" : "=r"(a) : "l"(p));
    return a;
}
__device__ __forceinline__ void cp16(uint32_t dst, const void* src) {
    size_t g;
    asm("cvta.to.global.u64 %0, %1;" : "=l"(g) : "l"(src));
    asm volatile("cp.async.cg.shared.global [%0], [%1], 16;" :: "r"(dst), "l"(g) : "memory");
}
#define CP_COMMIT() asm volatile("cp.async.commit_group;" ::: "memory")
#define CP_WAIT2()  asm volatile("cp.async.wait_group 2;" ::: "memory")

#define MMA_F16(d, a, b0, b1) \
    asm volatile("mma.sync.aligned.m16n8k16.row.col.f32.f16.f16.f32 " \
        "{%0,%1,%2,%3}, {%4,%5,%6,%7}, {%8,%9}, {%0,%1,%2,%3};" \
        : "+f"((d)[0]), "+f"((d)[1]), "+f"((d)[2]), "+f"((d)[3]) \
        : "r"((a)[0]), "r"((a)[1]), "r"((a)[2]), "r"((a)[3]), "r"(b0), "r"(b1))

__device__ __forceinline__ void ldm_x4(uint32_t* r, uint32_t a) {
    asm volatile("ldmatrix.sync.aligned.m8n8.x4.shared.b16 {%0,%1,%2,%3}, [%4];"
                 : "=r"(r[0]), "=r"(r[1]), "=r"(r[2]), "=r"(r[3]) : "r"(a));
}
__device__ __forceinline__ void hsplit(float x, __half& h, __half& l) {
    h = __float2half_rn(x);
    l = __float2half_rn(x - __half2float(h));
}
__device__ __forceinline__ void store_pk(__half* base, size_t row, int k,
                                         float v0, float v1) {
    const size_t dst = row * 2048 + (size_t)((k >> 4) * 32 + (k & 15));
    __half h0, l0, h1, l1;
    hsplit(v0, h0, l0); hsplit(v1, h1, l1);
    __half2 hp; hp.x = h0; hp.y = h1;
    __half2 lp; lp.x = l0; lp.y = l1;
    *(__half2*)(base + dst)      = hp;
    *(__half2*)(base + dst + 16) = lp;
}

// ===================== K1: weighted segment-sum -> u_pk =====================
__global__ __launch_bounds__(256)
void k_seg(const float* __restrict__ E_S, const float* __restrict__ W,
           const int* __restrict__ part_idx)
{
    __shared__ float w_s[2 * KK];
    __shared__ float winv_s[2 * PP];
    __shared__ int   pidx_s[KK];

    const int tid = threadIdx.x;
    const int bx  = blockIdx.x;
    const int row0 = bx * 2;

    if (tid < KK)  pidx_s[tid] = part_idx[tid];
    if (tid < 2 * KK) w_s[tid] = W[(size_t)row0 * KK + tid];
    __syncthreads();
    if (tid < 2 * PP) {
        int r = tid >> 2, p = tid & 3;
        float s = 0.f;
#pragma unroll
        for (int kp = 0; kp < KPP; kp++) s += w_s[r * KK + pidx_s[p * KPP + kp]];
        winv_s[tid] = 1.0f / (s + 1e-6f);
    }
    __syncthreads();

    const int p0 = tid >> 6;
    const int d4 = tid & 63;
    const float4* Ea = (const float4*)(E_S + (size_t)row0 * KK * DD);
    const float4* Eb = Ea + (KK * DD / 4);

    float4 aa = make_float4(0.f,0.f,0.f,0.f);
    float4 ab = make_float4(0.f,0.f,0.f,0.f);
#pragma unroll
    for (int kp = 0; kp < KPP; kp++) {
        const int k  = pidx_s[p0 * KPP + kp];
        const float wa = w_s[k];
        const float wb = w_s[KK + k];
        const float4 ea = Ea[k * 64 + d4];
        const float4 eb = Eb[k * 64 + d4];
        aa.x = fmaf(wa, ea.x, aa.x); aa.y = fmaf(wa, ea.y, aa.y);
        aa.z = fmaf(wa, ea.z, aa.z); aa.w = fmaf(wa, ea.w, aa.w);
        ab.x = fmaf(wb, eb.x, ab.x); ab.y = fmaf(wb, eb.y, ab.y);
        ab.z = fmaf(wb, eb.z, ab.z); ab.w = fmaf(wb, eb.w, ab.w);
    }
    const float iva = winv_s[p0];
    const float ivb = winv_s[PP + p0];
    aa.x *= iva; aa.y *= iva; aa.z *= iva; aa.w *= iva;
    ab.x *= ivb; ab.y *= ivb; ab.z *= ivb; ab.w *= ivb;

    const int kk = p0 * 256 + d4 * 4;
    store_pk(u_pk, row0,     kk,     aa.x, aa.y);
    store_pk(u_pk, row0,     kk + 2, aa.z, aa.w);
    store_pk(u_pk, row0 + 1, kk,     ab.x, ab.y);
    store_pk(u_pk, row0 + 1, kk + 2, ab.z, ab.w);
}

// ===================== prep: gv/cst + weight fp16 pack (hi only) ============
__global__ void k_prep(const float* __restrict__ v, const float* __restrict__ c,
                       const float* __restrict__ ln_g, const float* __restrict__ ln_b)
{
    const int tid = threadIdx.x;             // 128
    const int p = tid >> 5, lane = tid & 31;
    float s4 = 0.f, s5 = 0.f;
#pragma unroll
    for (int i = 0; i < 8; i++) {
        const int col = p * 256 + lane + i * 32;
        const float vv = v[col];
        const float g  = ln_g[col] * vv;
        const float b  = ln_b[col] * vv;
        gv_g[col] = g;
        s4 += g; s5 += b;
    }
#pragma unroll
    for (int off = 16; off; off >>= 1) {
        s4 += __shfl_xor_sync(0xffffffffu, s4, off);
        s5 += __shfl_xor_sync(0xffffffffu, s5, off);
    }
    if (lane == 0) { cst_g[p] = s4; cst_g[4 + p] = s5 + c[p]; }
}

__global__ __launch_bounds__(256)
void k_wconv(const float* __restrict__ part_W, const float* __restrict__ proj_W)
{
    const int i0 = blockIdx.x * 256 + threadIdx.x;
#pragma unroll
    for (int j = 0; j < 4; j++) {
        const int i = i0 + j * 131072;
        if (i < 262144) {
            const int row = i >> 8, k = i & 255;
            pw_pk[row * 512 + (k >> 4) * 32 + (k & 15)] = __float2half_rn(part_W[i]);
        } else {
            const int q = i - 262144;
            const int row = q >> 10, k = q & 1023;
            qw_pk[row * 2048 + (k >> 4) * 32 + (k & 15)] = __float2half_rn(proj_W[q]);
        }
    }
}

// ===================== 64x256-tile fp16 2-combo GEMM, 4-deep ring ===========
// smem row pitch 80B. A row: [hi q0 | hi q1 | lo q0 | lo q1 | pad16]
// B row: [hi q0 | hi q1 | (unused 48B)]  — identical pitch, proven conflict-free
#define PITCH 80
#define ASTG  5120
#define STG   25600
#define SM_TBL   102400
#define SM_BIAS  (SM_TBL)
#define SM_GVS   (SM_TBL + 1024)
#define SM_STATS (SM_TBL + 2048)
#define SM_ALPH  (SM_TBL + 2048 + 3072)
#define GEMM_SMEM (SM_ALPH + 256)

__global__ __launch_bounds__(256, 2)
void k_gemm(const float* __restrict__ part_b_, int mode)
{
    extern __shared__ char sm[];
    float* bias_s  = (float*)(sm + SM_BIAS);
    float* gvs_s   = (float*)(sm + SM_GVS);
    float* stats_s = (float*)(sm + SM_STATS);   // [64][12]
    float* alpha_s = (float*)(sm + SM_ALPH);    // [64]

    const int tid = threadIdx.x;
    const int w = tid >> 5, lane = tid & 31;
    const int gid = lane >> 2, tig = lane & 3;
    const int m0 = blockIdx.x * 64;
    const int by = blockIdx.y;     // mode0: part; mode1: K-split

    const __half *Asrc, *Bsrc;
    int aCh0, bCh0, bRowStride;
    if (mode == 0) {
        Asrc = u_pk; aCh0 = by * 16;
        Bsrc = pw_pk + by * 256 * 512; bRowStride = 512; bCh0 = 0;
        bias_s[tid] = part_b_[by * 256 + tid];
        gvs_s[tid]  = gv_g[by * 256 + tid];
    } else {
        Asrc = z_pk; aCh0 = by * 16;
        Bsrc = qw_pk; bRowStride = 2048; bCh0 = by * 16;
    }

    float acc[2][8][4];
#pragma unroll
    for (int mt = 0; mt < 2; mt++)
#pragma unroll
        for (int nt = 0; nt < 8; nt++)
#pragma unroll
            for (int q = 0; q < 4; q++) acc[mt][nt][q] = 0.f;

    auto issue = [&](int c) {
        if (c < 16) {
            char* base = sm + (c & 3) * STG;
#pragma unroll
            for (int j = 0; j < 3; j++) {
                const int s = tid + j * 256;
                if (s < 256) {          // A: 64 rows x 4 slots (hi q0,q1 / lo q0,q1)
                    const int row = s >> 2, q = s & 3;
                    cp16(smem_u32(base + row * PITCH + q * 16),
                         Asrc + (size_t)(m0 + row) * 2048 + (aCh0 + c) * 32 + q * 8);
                } else {                // B: 256 rows x 2 slots (hi q0,q1)
                    const int t = s - 256;
                    const int row = t >> 1, q = t & 1;
                    cp16(smem_u32(base + ASTG + row * PITCH + q * 16),
                         Bsrc + (size_t)row * bRowStride + (bCh0 + c) * 32 + q * 8);
                }
            }
        }
        CP_COMMIT();
    };

    issue(0); issue(1); issue(2);

    const int mrow = (w & 1) * 32;
    const int ncol = (w >> 1) * 64;
    const int lr = lane & 7, lq = lane >> 3;

#pragma unroll 1
    for (int c = 0; c < 16; c++) {
        CP_WAIT2();
        __syncthreads();
        issue(c + 3);

        char* base = sm + (c & 3) * STG;
        uint32_t ah[2][4], al[2][4];
#pragma unroll
        for (int mt = 0; mt < 2; mt++) {
            const uint32_t a = smem_u32(base + (mrow + mt * 16 + (lq & 1) * 8 + lr) * PITCH
                                        + (lq >> 1) * 16);
            ldm_x4(ah[mt], a);
            ldm_x4(al[mt], a + 32);
        }
#pragma unroll
        for (int np = 0; np < 2; np++) {       // pairs of n-tile-pairs
            uint32_t bh[2][4];
#pragma unroll
            for (int e = 0; e < 2; e++) {
                const int nt2 = np * 2 + e;
                const uint32_t b = smem_u32(base + ASTG
                                   + (ncol + nt2 * 16 + (lq >> 1) * 8 + lr) * PITCH
                                   + (lq & 1) * 16);
                ldm_x4(bh[e], b);
            }
#pragma unroll
            for (int e = 0; e < 2; e++) {      // combo hh
                const int nt2 = np * 2 + e;
                MMA_F16(acc[0][2*nt2],   ah[0], bh[e][0], bh[e][1]);
                MMA_F16(acc[0][2*nt2+1], ah[0], bh[e][2], bh[e][3]);
                MMA_F16(acc[1][2*nt2],   ah[1], bh[e][0], bh[e][1]);
                MMA_F16(acc[1][2*nt2+1], ah[1], bh[e][2], bh[e][3]);
            }
#pragma unroll
            for (int e = 0; e < 2; e++) {      // combo lh (A residual)
                const int nt2 = np * 2 + e;
                MMA_F16(acc[0][2*nt2],   al[0], bh[e][0], bh[e][1]);
                MMA_F16(acc[0][2*nt2+1], al[0], bh[e][2], bh[e][3]);
                MMA_F16(acc[1][2*nt2],   al[1], bh[e][0], bh[e][1]);
                MMA_F16(acc[1][2*nt2+1], al[1], bh[e][2], bh[e][3]);
            }
        }
    }

    if (mode == 0) {
        // ---- fused gate epilogue ----
        float s1[4], s2[4], s3[4];
#pragma unroll
        for (int i = 0; i < 4; i++) { s1[i] = 0.f; s2[i] = 0.f; s3[i] = 0.f; }
#pragma unroll
        for (int mt = 0; mt < 2; mt++)
#pragma unroll
            for (int nt = 0; nt < 8; nt++) {
                const int c0 = ncol + nt * 8 + tig * 2;
                const float b0 = bias_s[c0], b1 = bias_s[c0 + 1];
                const float g0 = gvs_s[c0],  g1 = gvs_s[c0 + 1];
                const float x0 = acc[mt][nt][0] + b0, x1 = acc[mt][nt][1] + b1;
                const float x2 = acc[mt][nt][2] + b0, x3 = acc[mt][nt][3] + b1;
                acc[mt][nt][0] = x0; acc[mt][nt][1] = x1;
                acc[mt][nt][2] = x2; acc[mt][nt][3] = x3;
                const int i0 = mt * 2, i1 = mt * 2 + 1;
                s1[i0] += x0 + x1; s2[i0] += x0*x0 + x1*x1; s3[i0] += x0*g0 + x1*g1;
                s1[i1] += x2 + x3; s2[i1] += x2*x2 + x3*x3; s3[i1] += x2*g0 + x3*g1;
            }
#pragma unroll
        for (int i = 0; i < 4; i++) {
#pragma unroll
            for (int off = 1; off < 4; off <<= 1) {
                s1[i] += __shfl_xor_sync(0xffffffffu, s1[i], off);
                s2[i] += __shfl_xor_sync(0xffffffffu, s2[i], off);
                s3[i] += __shfl_xor_sync(0xffffffffu, s3[i], off);
            }
        }
        const int cg = w >> 1;
        if (tig == 0) {
#pragma unroll
            for (int i = 0; i < 4; i++) {
                const int row = mrow + (i >> 1) * 16 + (i & 1) * 8 + gid;
                stats_s[row * 12 + cg * 3 + 0] = s1[i];
                stats_s[row * 12 + cg * 3 + 1] = s2[i];
                stats_s[row * 12 + cg * 3 + 2] = s3[i];
            }
        }
        __syncthreads();
        if (tid < 64) {
            float S1 = 0.f, S2 = 0.f, S3 = 0.f;
#pragma unroll
            for (int g = 0; g < 4; g++) {
                S1 += stats_s[tid * 12 + g * 3 + 0];
                S2 += stats_s[tid * 12 + g * 3 + 1];
                S3 += stats_s[tid * 12 + g * 3 + 2];
            }
            const float m   = S1 * (1.0f / DD);
            const float var = S2 * (1.0f / DD) - m * m;
            const float rs  = rsqrtf(var + 1e-5f);
            const float dot = rs * (S3 - m * cst_g[by]) + cst_g[4 + by];
            alpha_s[tid] = 1.0f / (1.0f + __expf(-dot));
        }
        __syncthreads();
#pragma unroll
        for (int mt = 0; mt < 2; mt++) {
            const int rA = mrow + mt * 16 + gid;
            const float alA = alpha_s[rA], alB = alpha_s[rA + 8];
#pragma unroll
            for (int nt = 0; nt < 8; nt++) {
                const int c0 = ncol + nt * 8 + tig * 2;
                const int k  = by * 256 + c0;
                store_pk(z_pk, (size_t)(m0 + rA),     k, acc[mt][nt][0] * alA, acc[mt][nt][1] * alA);
                store_pk(z_pk, (size_t)(m0 + rA + 8), k, acc[mt][nt][2] * alB, acc[mt][nt][3] * alB);
            }
        }
    } else {
        float* outp = s4_g + (size_t)by * BT * 256;
#pragma unroll
        for (int mt = 0; mt < 2; mt++) {
            const int r0 = m0 + mrow + mt * 16 + gid;
#pragma unroll
            for (int nt = 0; nt < 8; nt++) {
                const int c0 = ncol + nt * 8 + tig * 2;
                *(float2*)(outp + (size_t)r0 * 256 + c0) =
                    make_float2(acc[mt][nt][0], acc[mt][nt][1]);
                *(float2*)(outp + (size_t)(r0 + 8) * 256 + c0) =
                    make_float2(acc[mt][nt][2], acc[mt][nt][3]);
            }
        }
    }
}

// ===================== combine K-split partials + final LN ==================
__global__ __launch_bounds__(256)
void k_comb(const float* __restrict__ pjb, const float* __restrict__ og_,
            const float* __restrict__ ob_, float* __restrict__ out)
{
    __shared__ float redf[16 * 8 * 2];
    const int tid = threadIdx.x;
    const int w = tid >> 5, lane = tid & 31;
    const int bt0 = blockIdx.x * 16;

    const float b = pjb[tid];
    float x[16];
#pragma unroll
    for (int r = 0; r < 16; r++) {
        const size_t off = (size_t)(bt0 + r) * 256 + tid;
        x[r] = s4_g[off] + s4_g[off + (size_t)BT * 256]
             + s4_g[off + (size_t)2 * BT * 256] + s4_g[off + (size_t)3 * BT * 256] + b;
    }
#pragma unroll
    for (int r = 0; r < 16; r++) {
        float s1 = x[r], s2 = x[r] * x[r];
#pragma unroll
        for (int off = 16; off; off >>= 1) {
            s1 += __shfl_xor_sync(0xffffffffu, s1, off);
            s2 += __shfl_xor_sync(0xffffffffu, s2, off);
        }
        if (lane == 0) {
            redf[(r * 8 + w) * 2 + 0] = s1;
            redf[(r * 8 + w) * 2 + 1] = s2;
        }
    }
    __syncthreads();
    const float og = og_[tid], ob = ob_[tid];
#pragma unroll
    for (int r = 0; r < 16; r++) {
        float s1 = 0.f, s2 = 0.f;
#pragma unroll
        for (int ww = 0; ww < 8; ww++) {
            s1 += redf[(r * 8 + ww) * 2 + 0];
            s2 += redf[(r * 8 + ww) * 2 + 1];
        }
        const float m   = s1 * (1.0f / DD);
        const float var = s2 * (1.0f / DD) - m * m;
        const float rs  = rsqrtf(var + 1e-5f);
        out[(size_t)(bt0 + r) * 256 + tid] = (x[r] - m) * rs * og + ob;
    }
}

extern "C" void kernel_launch(void* const* d_in, const int* in_sizes, int n_in,
                              void* d_out, int out_size)
{
    (void)in_sizes; (void)n_in; (void)out_size;
    const float* E_S    = (const float*)d_in[0];
    const float* W      = (const float*)d_in[1];
    const int*   pidx   = (const int*)  d_in[2];
    const float* part_W = (const float*)d_in[3];
    const float* part_b = (const float*)d_in[4];
    const float* v      = (const float*)d_in[5];
    const float* c      = (const float*)d_in[6];
    const float* ln_g   = (const float*)d_in[7];
    const float* ln_b   = (const float*)d_in[8];
    const float* proj_W = (const float*)d_in[9];
    const float* proj_b = (const float*)d_in[10];
    const float* out_g  = (const float*)d_in[11];
    const float* out_b  = (const float*)d_in[12];
    float* out = (float*)d_out;

    cudaFuncSetAttribute(k_gemm, cudaFuncAttributeMaxDynamicSharedMemorySize, GEMM_SMEM);

    k_prep<<<1, 128>>>(v, c, ln_g, ln_b);
    k_wconv<<<512, 256>>>(part_W, proj_W);
    k_seg<<<BT / 2, 256>>>(E_S, W, pidx);
    k_gemm<<<dim3(64, 4), 256, GEMM_SMEM>>>(part_b, 0);
    k_gemm<<<dim3(64, 4), 256, GEMM_SMEM>>>(part_b, 1);
    k_comb<<<BT / 16, 256>>>(proj_b, out_g, out_b, out);
}

// round 17
// speedup vs baseline: 1.3567x; 1.0128x over previous
#include <cuda_runtime.h>
#include <cuda_fp16.h>
#include <math.h>
#include <stdint.h>

#define BT   4096
#define KK   64
#define DD   256
#define PP   4
#define KPP  16

// A-side packed hi|lo per 16-k chunk: [row][chunk][16 hi | 16 lo] fp16 (row stride 2048)
__device__ __align__(16) __half u_pk[(size_t)BT * 2048];
__device__ __align__(16) __half z_pk[(size_t)BT * 2048];
// B-side: same chunked layout, hi slots only
__device__ __align__(16) __half pw_pk[1024 * 512];
__device__ __align__(16) __half qw_pk[256 * 2048];
__device__ __align__(16) float s4_g[(size_t)2 * BT * 256];
__device__ __align__(16) float gv_g[1024];
__device__ float cst_g[8];

__device__ __forceinline__ uint32_t smem_u32(const void* p) {
    uint32_t a;
    asm("{ .reg .u64 t; cvta.to.shared.u64 t, %1; cvt.u32.u64 %0, t; }" : "=r"(a) : "l"(p));
    return a;
}
__device__ __forceinline__ void cp16(uint32_t dst, const void* src) {
    size_t g;
    asm("cvta.to.global.u64 %0, %1;" : "=l"(g) : "l"(src));
    asm volatile("cp.async.cg.shared.global [%0], [%1], 16;" :: "r"(dst), "l"(g) : "memory");
}
#define CP_COMMIT() asm volatile("cp.async.commit_group;" ::: "memory")
#define CP_WAIT2()  asm volatile("cp.async.wait_group 2;" ::: "memory")

#define MMA_F16(d, a, b0, b1) \
    asm volatile("mma.sync.aligned.m16n8k16.row.col.f32.f16.f16.f32 " \
        "{%0,%1,%2,%3}, {%4,%5,%6,%7}, {%8,%9}, {%0,%1,%2,%3};" \
        : "+f"((d)[0]), "+f"((d)[1]), "+f"((d)[2]), "+f"((d)[3]) \
        : "r"((a)[0]), "r"((a)[1]), "r"((a)[2]), "r"((a)[3]), "r"(b0), "r"(b1))

__device__ __forceinline__ void ldm_x4(uint32_t* r, uint32_t a) {
    asm volatile("ldmatrix.sync.aligned.m8n8.x4.shared.b16 {%0,%1,%2,%3}, [%4];"
                 : "=r"(r[0]), "=r"(r[1]), "=r"(r[2]), "=r"(r[3]) : "r"(a));
}
__device__ __forceinline__ void hsplit(float x, __half& h, __half& l) {
    h = __float2half_rn(x);
    l = __float2half_rn(x - __half2float(h));
}
__device__ __forceinline__ void store_pk(__half* base, size_t row, int k,
                                         float v0, float v1) {
    const size_t dst = row * 2048 + (size_t)((k >> 4) * 32 + (k & 15));
    __half h0, l0, h1, l1;
    hsplit(v0, h0, l0); hsplit(v1, h1, l1);
    __half2 hp; hp.x = h0; hp.y = h1;
    __half2 lp; lp.x = l0; lp.y = l1;
    *(__half2*)(base + dst)      = hp;
    *(__half2*)(base + dst + 16) = lp;
}

// ===================== K1: weighted segment-sum -> u_pk =====================
__global__ __launch_bounds__(256)
void k_seg(const float* __restrict__ E_S, const float* __restrict__ W,
           const int* __restrict__ part_idx)
{
    __shared__ float w_s[2 * KK];
    __shared__ float winv_s[2 * PP];
    __shared__ int   pidx_s[KK];

    const int tid = threadIdx.x;
    const int bx  = blockIdx.x;
    const int row0 = bx * 2;

    if (tid < KK)  pidx_s[tid] = part_idx[tid];
    if (tid < 2 * KK) w_s[tid] = W[(size_t)row0 * KK + tid];
    __syncthreads();
    if (tid < 2 * PP) {
        int r = tid >> 2, p = tid & 3;
        float s = 0.f;
#pragma unroll
        for (int kp = 0; kp < KPP; kp++) s += w_s[r * KK + pidx_s[p * KPP + kp]];
        winv_s[tid] = 1.0f / (s + 1e-6f);
    }
    __syncthreads();

    const int p0 = tid >> 6;
    const int d4 = tid & 63;
    const float4* Ea = (const float4*)(E_S + (size_t)row0 * KK * DD);
    const float4* Eb = Ea + (KK * DD / 4);

    float4 aa = make_float4(0.f,0.f,0.f,0.f);
    float4 ab = make_float4(0.f,0.f,0.f,0.f);
#pragma unroll
    for (int kp = 0; kp < KPP; kp++) {
        const int k  = pidx_s[p0 * KPP + kp];
        const float wa = w_s[k];
        const float wb = w_s[KK + k];
        const float4 ea = Ea[k * 64 + d4];
        const float4 eb = Eb[k * 64 + d4];
        aa.x = fmaf(wa, ea.x, aa.x); aa.y = fmaf(wa, ea.y, aa.y);
        aa.z = fmaf(wa, ea.z, aa.z); aa.w = fmaf(wa, ea.w, aa.w);
        ab.x = fmaf(wb, eb.x, ab.x); ab.y = fmaf(wb, eb.y, ab.y);
        ab.z = fmaf(wb, eb.z, ab.z); ab.w = fmaf(wb, eb.w, ab.w);
    }
    const float iva = winv_s[p0];
    const float ivb = winv_s[PP + p0];
    aa.x *= iva; aa.y *= iva; aa.z *= iva; aa.w *= iva;
    ab.x *= ivb; ab.y *= ivb; ab.z *= ivb; ab.w *= ivb;

    const int kk = p0 * 256 + d4 * 4;
    store_pk(u_pk, row0,     kk,     aa.x, aa.y);
    store_pk(u_pk, row0,     kk + 2, aa.z, aa.w);
    store_pk(u_pk, row0 + 1, kk,     ab.x, ab.y);
    store_pk(u_pk, row0 + 1, kk + 2, ab.z, ab.w);
}

// ===================== prep: gv/cst + weight fp16 pack (hi only) ============
__global__ void k_prep(const float* __restrict__ v, const float* __restrict__ c,
                       const float* __restrict__ ln_g, const float* __restrict__ ln_b)
{
    const int tid = threadIdx.x;             // 128
    const int p = tid >> 5, lane = tid & 31;
    float s4 = 0.f, s5 = 0.f;
#pragma unroll
    for (int i = 0; i < 8; i++) {
        const int col = p * 256 + lane + i * 32;
        const float vv = v[col];
        const float g  = ln_g[col] * vv;
        const float b  = ln_b[col] * vv;
        gv_g[col] = g;
        s4 += g; s5 += b;
    }
#pragma unroll
    for (int off = 16; off; off >>= 1) {
        s4 += __shfl_xor_sync(0xffffffffu, s4, off);
        s5 += __shfl_xor_sync(0xffffffffu, s5, off);
    }
    if (lane == 0) { cst_g[p] = s4; cst_g[4 + p] = s5 + c[p]; }
}

__global__ __launch_bounds__(256)
void k_wconv(const float* __restrict__ part_W, const float* __restrict__ proj_W)
{
    const int i0 = blockIdx.x * 256 + threadIdx.x;
#pragma unroll
    for (int j = 0; j < 4; j++) {
        const int i = i0 + j * 131072;
        if (i < 262144) {
            const int row = i >> 8, k = i & 255;
            pw_pk[row * 512 + (k >> 4) * 32 + (k & 15)] = __float2half_rn(part_W[i]);
        } else {
            const int q = i - 262144;
            const int row = q >> 10, k = q & 1023;
            qw_pk[row * 2048 + (k >> 4) * 32 + (k & 15)] = __float2half_rn(proj_W[q]);
        }
    }
}

// ===================== G1: 64x256 fp16 2-combo GEMM + fused gate ============
#define PITCH 80
#define ASTG  5120
#define STG   25600
#define SM_TBL   102400
#define SM_BIAS  (SM_TBL)
#define SM_GVS   (SM_TBL + 1024)
#define SM_STATS (SM_TBL + 2048)
#define SM_ALPH  (SM_TBL + 2048 + 3072)
#define GEMM_SMEM (SM_ALPH + 256)

__global__ __launch_bounds__(256, 2)
void k_gemm(const float* __restrict__ part_b_)
{
    extern __shared__ char sm[];
    float* bias_s  = (float*)(sm + SM_BIAS);
    float* gvs_s   = (float*)(sm + SM_GVS);
    float* stats_s = (float*)(sm + SM_STATS);   // [64][12]
    float* alpha_s = (float*)(sm + SM_ALPH);    // [64]

    const int tid = threadIdx.x;
    const int w = tid >> 5, lane = tid & 31;
    const int gid = lane >> 2, tig = lane & 3;
    const int m0 = blockIdx.x * 64;
    const int by = blockIdx.y;     // part

    const __half* Asrc = u_pk;
    const __half* Bsrc = pw_pk + by * 256 * 512;
    const int aCh0 = by * 16;
    bias_s[tid] = part_b_[by * 256 + tid];
    gvs_s[tid]  = gv_g[by * 256 + tid];

    float acc[2][8][4];
#pragma unroll
    for (int mt = 0; mt < 2; mt++)
#pragma unroll
        for (int nt = 0; nt < 8; nt++)
#pragma unroll
            for (int q = 0; q < 4; q++) acc[mt][nt][q] = 0.f;

    auto issue = [&](int c) {
        if (c < 16) {
            char* base = sm + (c & 3) * STG;
#pragma unroll
            for (int j = 0; j < 3; j++) {
                const int s = tid + j * 256;
                if (s < 256) {
                    const int row = s >> 2, q = s & 3;
                    cp16(smem_u32(base + row * PITCH + q * 16),
                         Asrc + (size_t)(m0 + row) * 2048 + (aCh0 + c) * 32 + q * 8);
                } else {
                    const int t = s - 256;
                    const int row = t >> 1, q = t & 1;
                    cp16(smem_u32(base + ASTG + row * PITCH + q * 16),
                         Bsrc + (size_t)row * 512 + c * 32 + q * 8);
                }
            }
        }
        CP_COMMIT();
    };

    issue(0); issue(1); issue(2);

    const int mrow = (w & 1) * 32;
    const int ncol = (w >> 1) * 64;
    const int lr = lane & 7, lq = lane >> 3;

#pragma unroll 1
    for (int c = 0; c < 16; c++) {
        CP_WAIT2();
        __syncthreads();
        issue(c + 3);

        char* base = sm + (c & 3) * STG;
        uint32_t ah[2][4], al[2][4];
#pragma unroll
        for (int mt = 0; mt < 2; mt++) {
            const uint32_t a = smem_u32(base + (mrow + mt * 16 + (lq & 1) * 8 + lr) * PITCH
                                        + (lq >> 1) * 16);
            ldm_x4(ah[mt], a);
            ldm_x4(al[mt], a + 32);
        }
#pragma unroll
        for (int np = 0; np < 2; np++) {
            uint32_t bh[2][4];
#pragma unroll
            for (int e = 0; e < 2; e++) {
                const int nt2 = np * 2 + e;
                const uint32_t b = smem_u32(base + ASTG
                                   + (ncol + nt2 * 16 + (lq >> 1) * 8 + lr) * PITCH
                                   + (lq & 1) * 16);
                ldm_x4(bh[e], b);
            }
#pragma unroll
            for (int e = 0; e < 2; e++) {
                const int nt2 = np * 2 + e;
                MMA_F16(acc[0][2*nt2],   ah[0], bh[e][0], bh[e][1]);
                MMA_F16(acc[0][2*nt2+1], ah[0], bh[e][2], bh[e][3]);
                MMA_F16(acc[1][2*nt2],   ah[1], bh[e][0], bh[e][1]);
                MMA_F16(acc[1][2*nt2+1], ah[1], bh[e][2], bh[e][3]);
            }
#pragma unroll
            for (int e = 0; e < 2; e++) {
                const int nt2 = np * 2 + e;
                MMA_F16(acc[0][2*nt2],   al[0], bh[e][0], bh[e][1]);
                MMA_F16(acc[0][2*nt2+1], al[0], bh[e][2], bh[e][3]);
                MMA_F16(acc[1][2*nt2],   al[1], bh[e][0], bh[e][1]);
                MMA_F16(acc[1][2*nt2+1], al[1], bh[e][2], bh[e][3]);
            }
        }
    }

    // ---- fused gate epilogue ----
    float s1[4], s2[4], s3[4];
#pragma unroll
    for (int i = 0; i < 4; i++) { s1[i] = 0.f; s2[i] = 0.f; s3[i] = 0.f; }
#pragma unroll
    for (int mt = 0; mt < 2; mt++)
#pragma unroll
        for (int nt = 0; nt < 8; nt++) {
            const int c0 = ncol + nt * 8 + tig * 2;
            const float b0 = bias_s[c0], b1 = bias_s[c0 + 1];
            const float g0 = gvs_s[c0],  g1 = gvs_s[c0 + 1];
            const float x0 = acc[mt][nt][0] + b0, x1 = acc[mt][nt][1] + b1;
            const float x2 = acc[mt][nt][2] + b0, x3 = acc[mt][nt][3] + b1;
            acc[mt][nt][0] = x0; acc[mt][nt][1] = x1;
            acc[mt][nt][2] = x2; acc[mt][nt][3] = x3;
            const int i0 = mt * 2, i1 = mt * 2 + 1;
            s1[i0] += x0 + x1; s2[i0] += x0*x0 + x1*x1; s3[i0] += x0*g0 + x1*g1;
            s1[i1] += x2 + x3; s2[i1] += x2*x2 + x3*x3; s3[i1] += x2*g0 + x3*g1;
        }
#pragma unroll
    for (int i = 0; i < 4; i++) {
#pragma unroll
        for (int off = 1; off < 4; off <<= 1) {
            s1[i] += __shfl_xor_sync(0xffffffffu, s1[i], off);
            s2[i] += __shfl_xor_sync(0xffffffffu, s2[i], off);
            s3[i] += __shfl_xor_sync(0xffffffffu, s3[i], off);
        }
    }
    const int cg = w >> 1;
    if (tig == 0) {
#pragma unroll
        for (int i = 0; i < 4; i++) {
            const int row = mrow + (i >> 1) * 16 + (i & 1) * 8 + gid;
            stats_s[row * 12 + cg * 3 + 0] = s1[i];
            stats_s[row * 12 + cg * 3 + 1] = s2[i];
            stats_s[row * 12 + cg * 3 + 2] = s3[i];
        }
    }
    __syncthreads();
    if (tid < 64) {
        float S1 = 0.f, S2 = 0.f, S3 = 0.f;
#pragma unroll
        for (int g = 0; g < 4; g++) {
            S1 += stats_s[tid * 12 + g * 3 + 0];
            S2 += stats_s[tid * 12 + g * 3 + 1];
            S3 += stats_s[tid * 12 + g * 3 + 2];
        }
        const float m   = S1 * (1.0f / DD);
        const float var = S2 * (1.0f / DD) - m * m;
        const float rs  = rsqrtf(var + 1e-5f);
        const float dot = rs * (S3 - m * cst_g[by]) + cst_g[4 + by];
        alpha_s[tid] = 1.0f / (1.0f + __expf(-dot));
    }
    __syncthreads();
#pragma unroll
    for (int mt = 0; mt < 2; mt++) {
        const int rA = mrow + mt * 16 + gid;
        const float alA = alpha_s[rA], alB = alpha_s[rA + 8];
#pragma unroll
        for (int nt = 0; nt < 8; nt++) {
            const int c0 = ncol + nt * 8 + tig * 2;
            const int k  = by * 256 + c0;
            store_pk(z_pk, (size_t)(m0 + rA),     k, acc[mt][nt][0] * alA, acc[mt][nt][1] * alA);
            store_pk(z_pk, (size_t)(m0 + rA + 8), k, acc[mt][nt][2] * alB, acc[mt][nt][3] * alB);
        }
    }
}

// ===================== G2: 32x256 tile, 2-way K-split, 32 chunks ============
#define ASTG2  2560
#define STG2   23040
#define GEMM2_SMEM (4 * STG2)    // 92160

__global__ __launch_bounds__(256, 2)
void k_gemm2()
{
    extern __shared__ char sm[];

    const int tid = threadIdx.x;
    const int w = tid >> 5, lane = tid & 31;
    const int gid = lane >> 2, tig = lane & 3;
    const int m0 = blockIdx.x * 32;
    const int ks = blockIdx.y;     // K half

    const __half* Asrc = z_pk;
    const __half* Bsrc = qw_pk;
    const int ch0 = ks * 32;

    float acc[8][4];
#pragma unroll
    for (int nt = 0; nt < 8; nt++)
#pragma unroll
        for (int q = 0; q < 4; q++) acc[nt][q] = 0.f;

    auto issue = [&](int c) {
        if (c < 32) {
            char* base = sm + (c & 3) * STG2;
#pragma unroll
            for (int j = 0; j < 3; j++) {
                const int s = tid + j * 256;
                if (s < 128) {           // A: 32 rows x 4 slots
                    const int row = s >> 2, q = s & 3;
                    cp16(smem_u32(base + row * PITCH + q * 16),
                         Asrc + (size_t)(m0 + row) * 2048 + (ch0 + c) * 32 + q * 8);
                } else if (s < 640) {    // B: 256 rows x 2 slots
                    const int t = s - 128;
                    const int row = t >> 1, q = t & 1;
                    cp16(smem_u32(base + ASTG2 + row * PITCH + q * 16),
                         Bsrc + (size_t)row * 2048 + (ch0 + c) * 32 + q * 8);
                }
            }
        }
        CP_COMMIT();
    };

    issue(0); issue(1); issue(2);

    const int mrow = (w & 1) * 16;
    const int ncol = (w >> 1) * 64;
    const int lr = lane & 7, lq = lane >> 3;

#pragma unroll 1
    for (int c = 0; c < 32; c++) {
        CP_WAIT2();
        __syncthreads();
        issue(c + 3);

        char* base = sm + (c & 3) * STG2;
        uint32_t ah[4], al[4];
        {
            const uint32_t a = smem_u32(base + (mrow + (lq & 1) * 8 + lr) * PITCH
                                        + (lq >> 1) * 16);
            ldm_x4(ah, a);
            ldm_x4(al, a + 32);
        }
#pragma unroll
        for (int np = 0; np < 2; np++) {
            uint32_t bh[2][4];
#pragma unroll
            for (int e = 0; e < 2; e++) {
                const int nt2 = np * 2 + e;
                const uint32_t b = smem_u32(base + ASTG2
                                   + (ncol + nt2 * 16 + (lq >> 1) * 8 + lr) * PITCH
                                   + (lq & 1) * 16);
                ldm_x4(bh[e], b);
            }
#pragma unroll
            for (int e = 0; e < 2; e++) {
                const int nt2 = np * 2 + e;
                MMA_F16(acc[2*nt2],   ah, bh[e][0], bh[e][1]);
                MMA_F16(acc[2*nt2+1], ah, bh[e][2], bh[e][3]);
            }
#pragma unroll
            for (int e = 0; e < 2; e++) {
                const int nt2 = np * 2 + e;
                MMA_F16(acc[2*nt2],   al, bh[e][0], bh[e][1]);
                MMA_F16(acc[2*nt2+1], al, bh[e][2], bh[e][3]);
            }
        }
    }

    float* outp = s4_g + (size_t)ks * BT * 256;
    const int r0 = m0 + mrow + gid;
#pragma unroll
    for (int nt = 0; nt < 8; nt++) {
        const int c0 = ncol + nt * 8 + tig * 2;
        *(float2*)(outp + (size_t)r0 * 256 + c0) =
            make_float2(acc[nt][0], acc[nt][1]);
        *(float2*)(outp + (size_t)(r0 + 8) * 256 + c0) =
            make_float2(acc[nt][2], acc[nt][3]);
    }
}

// ===================== combine 2 K-split partials + final LN ================
__global__ __launch_bounds__(256)
void k_comb(const float* __restrict__ pjb, const float* __restrict__ og_,
            const float* __restrict__ ob_, float* __restrict__ out)
{
    __shared__ float redf[16 * 8 * 2];
    const int tid = threadIdx.x;
    const int w = tid >> 5, lane = tid & 31;
    const int bt0 = blockIdx.x * 16;

    const float b = pjb[tid];
    float x[16];
#pragma unroll
    for (int r = 0; r < 16; r++) {
        const size_t off = (size_t)(bt0 + r) * 256 + tid;
        x[r] = s4_g[off] + s4_g[off + (size_t)BT * 256] + b;
    }
#pragma unroll
    for (int r = 0; r < 16; r++) {
        float s1 = x[r], s2 = x[r] * x[r];
#pragma unroll
        for (int off = 16; off; off >>= 1) {
            s1 += __shfl_xor_sync(0xffffffffu, s1, off);
            s2 += __shfl_xor_sync(0xffffffffu, s2, off);
        }
        if (lane == 0) {
            redf[(r * 8 + w) * 2 + 0] = s1;
            redf[(r * 8 + w) * 2 + 1] = s2;
        }
    }
    __syncthreads();
    const float og = og_[tid], ob = ob_[tid];
#pragma unroll
    for (int r = 0; r < 16; r++) {
        float s1 = 0.f, s2 = 0.f;
#pragma unroll
        for (int ww = 0; ww < 8; ww++) {
            s1 += redf[(r * 8 + ww) * 2 + 0];
            s2 += redf[(r * 8 + ww) * 2 + 1];
        }
        const float m   = s1 * (1.0f / DD);
        const float var = s2 * (1.0f / DD) - m * m;
        const float rs  = rsqrtf(var + 1e-5f);
        out[(size_t)(bt0 + r) * 256 + tid] = (x[r] - m) * rs * og + ob;
    }
}

extern "C" void kernel_launch(void* const* d_in, const int* in_sizes, int n_in,
                              void* d_out, int out_size)
{
    (void)in_sizes; (void)n_in; (void)out_size;
    const float* E_S    = (const float*)d_in[0];
    const float* W      = (const float*)d_in[1];
    const int*   pidx   = (const int*)  d_in[2];
    const float* part_W = (const float*)d_in[3];
    const float* part_b = (const float*)d_in[4];
    const float* v      = (const float*)d_in[5];
    const float* c      = (const float*)d_in[6];
    const float* ln_g   = (const float*)d_in[7];
    const float* ln_b   = (const float*)d_in[8];
    const float* proj_W = (const float*)d_in[9];
    const float* proj_b = (const float*)d_in[10];
    const float* out_g  = (const float*)d_in[11];
    const float* out_b  = (const float*)d_in[12];
    float* out = (float*)d_out;

    cudaFuncSetAttribute(k_gemm,  cudaFuncAttributeMaxDynamicSharedMemorySize, GEMM_SMEM);
    cudaFuncSetAttribute(k_gemm2, cudaFuncAttributeMaxDynamicSharedMemorySize, GEMM2_SMEM);

    k_prep<<<1, 128>>>(v, c, ln_g, ln_b);
    k_wconv<<<512, 256>>>(part_W, proj_W);
    k_seg<<<BT / 2, 256>>>(E_S, W, pidx);
    k_gemm<<<dim3(64, 4), 256, GEMM_SMEM>>>(part_b);
    k_gemm2<<<dim3(128, 2), 256, GEMM2_SMEM>>>();
    k_comb<<<BT / 16, 256>>>(proj_b, out_g, out_b, out);
}